// round 15
// baseline (speedup 1.0000x reference)
#include <cuda_runtime.h>
#include <cuda_bf16.h>

// y[t, f] = x[t, f] * w[f] + b[f]
// x: [8192, 4096] f32 (128 MiB), w/b: [4096] f32, out: same shape.
//
// FINAL: pure HBM streaming at the measured optimum for sm_103a.
// Search ladder (kernel time):
//  - width: LDG.128 optimal; 256-bit v8 loads tank L1tex (66us).
//  - ILP:   1->39.0, 2->36.1, 4->35.3 (ridge), 8->39.8 (occ+L1tex queue loss).
//  - block: 256 (35.3) >= 512 (35.8). Persistent grid-stride: 39.7 (loses).
//  - cache policy: default best; evict_last pinning, .cs loads/stores all
//    neutral-to-negative.
// Result: 35.3us, 6.05 TB/s HBM (76% spec), 7.6 TB/s effective w/ L2 replay
// hits — at the r/w-mix LTS/DRAM efficiency ceiling.

#define TOKENS      8192
#define IN_FEATURES 4096
#define COLS4       (IN_FEATURES / 4)    // 1024, pow2
#define N4          (TOKENS * COLS4)     // 8,388,608 quads
#define Q4          (N4 / 4)             // 2,097,152 (multiple of COLS4)

__global__ __launch_bounds__(256) void one_to_one_kernel(
    const float4* __restrict__ x,
    const float4* __restrict__ w,
    const float4* __restrict__ b,
    float4* __restrict__ out)
{
    int i = blockIdx.x * blockDim.x + threadIdx.x;   // 0 .. Q4-1
    int c = i & (COLS4 - 1);                         // same column for all 4 quads

    // Four independent streaming loads, front-batched for deep MLP
    float4 x0 = x[i];
    float4 x1 = x[i + Q4];
    float4 x2 = x[i + 2 * Q4];
    float4 x3 = x[i + 3 * Q4];

    float4 wv = __ldg(&w[c]);
    float4 bv = __ldg(&b[c]);

    float4 r0, r1, r2, r3;
    r0.x = fmaf(x0.x, wv.x, bv.x); r0.y = fmaf(x0.y, wv.y, bv.y);
    r0.z = fmaf(x0.z, wv.z, bv.z); r0.w = fmaf(x0.w, wv.w, bv.w);
    r1.x = fmaf(x1.x, wv.x, bv.x); r1.y = fmaf(x1.y, wv.y, bv.y);
    r1.z = fmaf(x1.z, wv.z, bv.z); r1.w = fmaf(x1.w, wv.w, bv.w);
    r2.x = fmaf(x2.x, wv.x, bv.x); r2.y = fmaf(x2.y, wv.y, bv.y);
    r2.z = fmaf(x2.z, wv.z, bv.z); r2.w = fmaf(x2.w, wv.w, bv.w);
    r3.x = fmaf(x3.x, wv.x, bv.x); r3.y = fmaf(x3.y, wv.y, bv.y);
    r3.z = fmaf(x3.z, wv.z, bv.z); r3.w = fmaf(x3.w, wv.w, bv.w);

    out[i]          = r0;
    out[i + Q4]     = r1;
    out[i + 2 * Q4] = r2;
    out[i + 3 * Q4] = r3;
}

extern "C" void kernel_launch(void* const* d_in, const int* in_sizes, int n_in,
                              void* d_out, int out_size)
{
    const float4* x = (const float4*)d_in[0];
    const float4* w = (const float4*)d_in[1];
    const float4* b = (const float4*)d_in[2];
    float4* out = (float4*)d_out;

    const int threads = 256;
    const int blocks  = Q4 / threads;   // 8192
    one_to_one_kernel<<<blocks, threads>>>(x, w, b, out);
}